// round 8
// baseline (speedup 1.0000x reference)
#include <cuda_runtime.h>
#include <cuda_bf16.h>
#include <cstdint>

#define NPTS 1024
#define HDIM 32

typedef unsigned long long u64;
typedef unsigned int u32;

// ---------- scratch ----------
__device__ float g_a[NPTS * HDIM];
__device__ float g_c[(NPTS + 4) * HDIM];   // +4 zero pad rows (prefetch overrun)
__device__ float g_h1[NPTS * HDIM];

// ---------- packed f32x2 helpers ----------
__device__ __forceinline__ u64 f2fma(u64 a, u64 b, u64 c) {
    u64 d;
    asm("fma.rn.f32x2 %0, %1, %2, %3;" : "=l"(d) : "l"(a), "l"(b), "l"(c));
    return d;
}
__device__ __forceinline__ u64 add2(u64 a, u64 b) {
    u64 d;
    asm("add.rn.f32x2 %0, %1, %2;" : "=l"(d) : "l"(a), "l"(b));
    return d;
}
__device__ __forceinline__ u64 pack2(float lo, float hi) {
    u64 r;
    asm("mov.b64 %0, {%1, %2};" : "=l"(r) : "f"(lo), "f"(hi));
    return r;
}
__device__ __forceinline__ void unpack2(float& lo, float& hi, u64 v) {
    asm("mov.b64 {%0, %1}, %2;" : "=f"(lo), "=f"(hi) : "l"(v));
}
__device__ __forceinline__ float hsum2(u64 v) {
    float lo, hi;
    unpack2(lo, hi, v);
    return lo + hi;
}
__device__ __forceinline__ float tanh_hw(float x) {
    float y;
    asm("tanh.approx.f32 %0, %1;" : "=f"(y) : "f"(x));
    return y;
}
__device__ __forceinline__ float sig_hw(float x) {
    return fmaf(tanh_hw(0.5f * x), 0.5f, 0.5f);
}
__device__ __forceinline__ u32 smem_u32(const void* p) {
    u32 a;
    asm("{ .reg .u64 t; cvta.to.shared.u64 t, %1; cvt.u32.u64 %0, t; }"
        : "=r"(a) : "l"(p));
    return a;
}
__device__ __forceinline__ void sts32(u32 addr, float v) {
    asm volatile("st.shared.b32 [%0], %1;" :: "r"(addr), "f"(v) : "memory");
}
__device__ __forceinline__ void lds_v2(u64& p0, u64& p1, u32 addr) {
    asm volatile("ld.shared.v2.u64 {%0, %1}, [%2];"
                 : "=l"(p0), "=l"(p1) : "r"(addr));
}

// ---------- precompute: a_i = (Wa-Wb)@x_i + b ; c_j = Wb@x_j ----------
template <int F>
__global__ void __launch_bounds__(256)
pre_kernel(const float* __restrict__ x, const float* __restrict__ w,
           const float* __restrict__ b, float* __restrict__ a,
           float* __restrict__ c) {
    int wq = threadIdx.x >> 5;
    int l = threadIdx.x & 31;
    int i = blockIdx.x * 8 + wq;
    if (i >= NPTS) return;
    float av = b[l];
    float cv = 0.0f;
    const float* wr = w + l * (2 * F);
    const float* xr = x + i * F;
#pragma unroll
    for (int f = 0; f < F; ++f) {
        float xv = xr[f];
        float wa = wr[f];
        float wb = wr[F + f];
        av = fmaf(wa - wb, xv, av);
        cv = fmaf(wb, xv, cv);
    }
    a[i * HDIM + l] = av;
    c[i * HDIM + l] = cv;
}

// ---------- GRU scan: 2 sequences per warp (shared weight regs) ----------
// Streams A/B are independent scans; their chains interleave to hide latency.
// Schedule per step: publish -> hgA(dual chains) -> hgB(single chains) ->
// tailA -> xgA -> tailB -> xgB.
template <int FUSE_CLF>
__global__ void __launch_bounds__(64, 2)
gru_scan_kernel(const float* __restrict__ a, const float* __restrict__ c,
                const float* __restrict__ wih, const float* __restrict__ whh,
                const float* __restrict__ bih, const float* __restrict__ bhh,
                const float* __restrict__ clf_w, const float* __restrict__ clf_b,
                float* __restrict__ out) {
    __shared__ __align__(16) float s_u[2][2][2][HDIM];  // [warp][stream][buf][lane]
    __shared__ __align__(16) float s_h[2][2][2][HDIM];

    const int w = threadIdx.x >> 5;
    const int l = threadIdx.x & 31;
    const int iA = blockIdx.x * 4 + w * 2;
    const int iB = iA + 1;

    // Weight rows as adjacent-k u64 pairs (96 u64 = 192 regs), shared by streams.
    u64 Wxr[16], Wxz[16], Wxn[16], Whr[16], Whz[16], Whn[16];
    {
        const u64* pxr = (const u64*)(wih + (0 * HDIM + l) * HDIM);
        const u64* pxz = (const u64*)(wih + (1 * HDIM + l) * HDIM);
        const u64* pxn = (const u64*)(wih + (2 * HDIM + l) * HDIM);
        const u64* phr = (const u64*)(whh + (0 * HDIM + l) * HDIM);
        const u64* phz = (const u64*)(whh + (1 * HDIM + l) * HDIM);
        const u64* phn = (const u64*)(whh + (2 * HDIM + l) * HDIM);
#pragma unroll
        for (int q = 0; q < 16; ++q) {
            Wxr[q] = pxr[q];
            Wxz[q] = pxz[q];
            Wxn[q] = pxn[q];
            Whr[q] = phr[q];
            Whz[q] = phz[q];
            Whn[q] = phn[q];
        }
    }

    // Biases as scalars (applied in the tail) to save registers.
    const float b_r = bih[l] + bhh[l];
    const float b_z = bih[HDIM + l] + bhh[HDIM + l];
    const float b_xn = bih[2 * HDIM + l];
    const float b_hn = bhh[2 * HDIM + l];

    const float aA = a[iA * HDIM + l];
    const float aB = a[iB * HDIM + l];

    const u32 ubA = smem_u32(&s_u[w][0][0][0]);
    const u32 hbA = smem_u32(&s_h[w][0][0][0]);
    const u32 ubB = smem_u32(&s_u[w][1][0][0]);
    const u32 hbB = smem_u32(&s_h[w][1][0][0]);

    float hA = 0.0f, hB = 0.0f;
    u64 xgA_r, xgA_z, xgA_n, xgB_r, xgB_z, xgB_n;

    // ---- prologue: xg_0 for both streams (staged via buf1) ----
    {
        const float c0 = c[l];
        sts32(ubA + 128u + l * 4u, fmaxf(aA + c0, 0.0f));
        sts32(ubB + 128u + l * 4u, fmaxf(aB + c0, 0.0f));
        __syncwarp();
        u64 r_ = 0ULL, z_ = 0ULL, n_ = 0ULL;
#pragma unroll
        for (int q = 0; q < 8; ++q) {
            u64 u0p, u1p;
            lds_v2(u0p, u1p, ubA + 128u + q * 16u);
            r_ = f2fma(Wxr[2 * q], u0p, f2fma(Wxr[2 * q + 1], u1p, r_));
            z_ = f2fma(Wxz[2 * q], u0p, f2fma(Wxz[2 * q + 1], u1p, z_));
            n_ = f2fma(Wxn[2 * q], u0p, f2fma(Wxn[2 * q + 1], u1p, n_));
        }
        xgA_r = r_; xgA_z = z_; xgA_n = n_;
        r_ = z_ = n_ = 0ULL;
#pragma unroll
        for (int q = 0; q < 8; ++q) {
            u64 u0p, u1p;
            lds_v2(u0p, u1p, ubB + 128u + q * 16u);
            r_ = f2fma(Wxr[2 * q], u0p, f2fma(Wxr[2 * q + 1], u1p, r_));
            z_ = f2fma(Wxz[2 * q], u0p, f2fma(Wxz[2 * q + 1], u1p, z_));
            n_ = f2fma(Wxn[2 * q], u0p, f2fma(Wxn[2 * q + 1], u1p, n_));
        }
        xgB_r = r_; xgB_z = z_; xgB_n = n_;
    }

    float cn = c[1 * HDIM + l];     // c_{j+1} (shared by both streams)
    float cn2 = c[2 * HDIM + l];

#define STEP_BODY(J, BOFF)                                                    \
    {                                                                         \
        const float uA = fmaxf(aA + cn, 0.0f);                                \
        const float uB = fmaxf(aB + cn, 0.0f);                                \
        cn = cn2;                                                             \
        cn2 = c[((J) + 3) * HDIM + l];                                        \
        sts32(hbA + (BOFF) + l * 4u, hA);                                     \
        sts32(ubA + (BOFF) + l * 4u, uA);                                     \
        sts32(hbB + (BOFF) + l * 4u, hB);                                     \
        sts32(ubB + (BOFF) + l * 4u, uB);                                     \
        __syncwarp();                                                         \
        /* hgA: dual chains (critical path of stream A) */                    \
        u64 arA0 = 0ULL, arA1 = 0ULL, azA0 = 0ULL, azA1 = 0ULL;               \
        u64 anA0 = 0ULL, anA1 = 0ULL;                                         \
        _Pragma("unroll")                                                     \
        for (int q = 0; q < 8; ++q) {                                         \
            u64 h0p, h1p;                                                     \
            lds_v2(h0p, h1p, hbA + (BOFF) + q * 16u);                         \
            arA0 = f2fma(Whr[2 * q], h0p, arA0);                              \
            arA1 = f2fma(Whr[2 * q + 1], h1p, arA1);                          \
            azA0 = f2fma(Whz[2 * q], h0p, azA0);                              \
            azA1 = f2fma(Whz[2 * q + 1], h1p, azA1);                          \
            anA0 = f2fma(Whn[2 * q], h0p, anA0);                              \
            anA1 = f2fma(Whn[2 * q + 1], h1p, anA1);                          \
        }                                                                     \
        /* hgB: single chains (filler for A's stalls) */                      \
        u64 rB_ = 0ULL, zB_ = 0ULL, nB_ = 0ULL;                               \
        _Pragma("unroll")                                                     \
        for (int q = 0; q < 8; ++q) {                                         \
            u64 h0p, h1p;                                                     \
            lds_v2(h0p, h1p, hbB + (BOFF) + q * 16u);                         \
            rB_ = f2fma(Whr[2 * q], h0p, f2fma(Whr[2 * q + 1], h1p, rB_));    \
            zB_ = f2fma(Whz[2 * q], h0p, f2fma(Whz[2 * q + 1], h1p, zB_));    \
            nB_ = f2fma(Whn[2 * q], h0p, f2fma(Whn[2 * q + 1], h1p, nB_));    \
        }                                                                     \
        /* tail A */                                                          \
        {                                                                     \
            const float r = sig_hw(hsum2(add2(xgA_r, add2(arA0, arA1))) + b_r); \
            const float z = sig_hw(hsum2(add2(xgA_z, add2(azA0, azA1))) + b_z); \
            const float xn_v = hsum2(xgA_n) + b_xn;                           \
            const float hn_v = hsum2(add2(anA0, anA1)) + b_hn;                \
            const float n = tanh_hw(fmaf(r, hn_v, xn_v));                     \
            hA = fmaf(z, hA - n, n);                                          \
        }                                                                     \
        /* xgA for next step (independent; fills tail stalls) */              \
        {                                                                     \
            u64 r_ = 0ULL, z_ = 0ULL, n_ = 0ULL;                              \
            _Pragma("unroll")                                                 \
            for (int q = 0; q < 8; ++q) {                                     \
                u64 u0p, u1p;                                                 \
                lds_v2(u0p, u1p, ubA + (BOFF) + q * 16u);                     \
                r_ = f2fma(Wxr[2 * q], u0p, f2fma(Wxr[2 * q + 1], u1p, r_));  \
                z_ = f2fma(Wxz[2 * q], u0p, f2fma(Wxz[2 * q + 1], u1p, z_));  \
                n_ = f2fma(Wxn[2 * q], u0p, f2fma(Wxn[2 * q + 1], u1p, n_));  \
            }                                                                 \
            xgA_r = r_; xgA_z = z_; xgA_n = n_;                               \
        }                                                                     \
        /* tail B */                                                          \
        {                                                                     \
            const float r = sig_hw(hsum2(add2(xgB_r, rB_)) + b_r);            \
            const float z = sig_hw(hsum2(add2(xgB_z, zB_)) + b_z);            \
            const float xn_v = hsum2(xgB_n) + b_xn;                           \
            const float hn_v = hsum2(nB_) + b_hn;                             \
            const float n = tanh_hw(fmaf(r, hn_v, xn_v));                     \
            hB = fmaf(z, hB - n, n);                                          \
        }                                                                     \
        /* xgB for next step */                                               \
        {                                                                     \
            u64 r_ = 0ULL, z_ = 0ULL, n_ = 0ULL;                              \
            _Pragma("unroll")                                                 \
            for (int q = 0; q < 8; ++q) {                                     \
                u64 u0p, u1p;                                                 \
                lds_v2(u0p, u1p, ubB + (BOFF) + q * 16u);                     \
                r_ = f2fma(Wxr[2 * q], u0p, f2fma(Wxr[2 * q + 1], u1p, r_));  \
                z_ = f2fma(Wxz[2 * q], u0p, f2fma(Wxz[2 * q + 1], u1p, z_));  \
                n_ = f2fma(Wxn[2 * q], u0p, f2fma(Wxn[2 * q + 1], u1p, n_));  \
            }                                                                 \
            xgB_r = r_; xgB_z = z_; xgB_n = n_;                               \
        }                                                                     \
    }

    for (int j = 0; j < NPTS; j += 2) {
        STEP_BODY(j, 0u)
        STEP_BODY(j + 1, 128u)
    }
#undef STEP_BODY

    if (FUSE_CLF) {
        sts32(hbA + l * 4u, hA);
        sts32(hbB + l * 4u, hB);
        __syncwarp();
        if (l < 3) {
            float accA = clf_b[l];
            float accB = clf_b[l];
            const float* cw = clf_w + l * HDIM;
#pragma unroll
            for (int hh = 0; hh < HDIM; ++hh) {
                accA = fmaf(cw[hh], s_h[w][0][0][hh], accA);
                accB = fmaf(cw[hh], s_h[w][1][0][hh], accB);
            }
            out[iA * 3 + l] = accA;
            out[iB * 3 + l] = accB;
        }
    } else {
        out[iA * HDIM + l] = hA;
        out[iB * HDIM + l] = hB;
    }
}

extern "C" void kernel_launch(void* const* d_in, const int* in_sizes, int n_in,
                              void* d_out, int out_size) {
    const float* x        = (const float*)d_in[0];
    const float* proj1_w  = (const float*)d_in[1];
    const float* proj1_b  = (const float*)d_in[2];
    const float* gru1_wih = (const float*)d_in[3];
    const float* gru1_whh = (const float*)d_in[4];
    const float* gru1_bih = (const float*)d_in[5];
    const float* gru1_bhh = (const float*)d_in[6];
    const float* proj2_w  = (const float*)d_in[7];
    const float* proj2_b  = (const float*)d_in[8];
    const float* gru2_wih = (const float*)d_in[9];
    const float* gru2_whh = (const float*)d_in[10];
    const float* gru2_bih = (const float*)d_in[11];
    const float* gru2_bhh = (const float*)d_in[12];
    const float* clf_w    = (const float*)d_in[13];
    const float* clf_b    = (const float*)d_in[14];
    float* out = (float*)d_out;

    float *pa, *pc, *ph1;
    cudaGetSymbolAddress((void**)&pa, g_a);
    cudaGetSymbolAddress((void**)&pc, g_c);
    cudaGetSymbolAddress((void**)&ph1, g_h1);

    pre_kernel<16><<<128, 256>>>(x, proj1_w, proj1_b, pa, pc);
    gru_scan_kernel<0><<<256, 64>>>(pa, pc, gru1_wih, gru1_whh, gru1_bih,
                                    gru1_bhh, nullptr, nullptr, ph1);
    pre_kernel<32><<<128, 256>>>(ph1, proj2_w, proj2_b, pa, pc);
    gru_scan_kernel<1><<<256, 64>>>(pa, pc, gru2_wih, gru2_whh, gru2_bih,
                                    gru2_bhh, clf_w, clf_b, out);
}

// round 9
// speedup vs baseline: 1.1244x; 1.1244x over previous
#include <cuda_runtime.h>
#include <cuda_bf16.h>
#include <cstdint>

#define NPTS 1024
#define HDIM 32
#define T_CHUNK 8
#define NCHUNK (NPTS / T_CHUNK)

typedef unsigned long long u64;
typedef unsigned int u32;

// ---------- scratch ----------
__device__ float g_a[NPTS * HDIM];
__device__ float g_c[(NPTS + 4) * HDIM];   // +4 zero pad rows (prefetch overrun)
__device__ float g_h1[NPTS * HDIM];

// ---------- packed f32x2 helpers ----------
__device__ __forceinline__ u64 f2fma(u64 a, u64 b, u64 c) {
    u64 d;
    asm("fma.rn.f32x2 %0, %1, %2, %3;" : "=l"(d) : "l"(a), "l"(b), "l"(c));
    return d;
}
__device__ __forceinline__ u64 pack2(float lo, float hi) {
    u64 r;
    asm("mov.b64 %0, {%1, %2};" : "=l"(r) : "f"(lo), "f"(hi));
    return r;
}
__device__ __forceinline__ float hsum2(u64 v) {
    float lo, hi;
    asm("mov.b64 {%0, %1}, %2;" : "=f"(lo), "=f"(hi) : "l"(v));
    return lo + hi;
}
__device__ __forceinline__ float tanh_hw(float x) {
    float y;
    asm("tanh.approx.f32 %0, %1;" : "=f"(y) : "f"(x));
    return y;
}
__device__ __forceinline__ float sig_hw(float x) {
    return fmaf(tanh_hw(0.5f * x), 0.5f, 0.5f);
}
__device__ __forceinline__ u32 smem_u32(const void* p) {
    u32 a;
    asm("{ .reg .u64 t; cvta.to.shared.u64 t, %1; cvt.u32.u64 %0, t; }"
        : "=r"(a) : "l"(p));
    return a;
}
__device__ __forceinline__ void sts32(u32 addr, float v) {
    asm volatile("st.shared.b32 [%0], %1;" :: "r"(addr), "f"(v) : "memory");
}
__device__ __forceinline__ float lds32f(u32 addr) {
    float v;
    asm volatile("ld.shared.b32 %0, [%1];" : "=f"(v) : "r"(addr));
    return v;
}
__device__ __forceinline__ void lds_v2(u64& p0, u64& p1, u32 addr) {
    asm volatile("ld.shared.v2.u64 {%0, %1}, [%2];"
                 : "=l"(p0), "=l"(p1) : "r"(addr));
}
__device__ __forceinline__ void barrier_all() {
    asm volatile("bar.sync 0;" ::: "memory");
}

// ---------- precompute: a_i = (Wa-Wb)@x_i + b ; c_j = Wb@x_j ----------
template <int F>
__global__ void __launch_bounds__(256)
pre_kernel(const float* __restrict__ x, const float* __restrict__ w,
           const float* __restrict__ b, float* __restrict__ a,
           float* __restrict__ c) {
    int wq = threadIdx.x >> 5;
    int l = threadIdx.x & 31;
    int i = blockIdx.x * 8 + wq;
    if (i >= NPTS) return;
    float av = b[l];
    float cv = 0.0f;
    const float* wr = w + l * (2 * F);
    const float* xr = x + i * F;
#pragma unroll
    for (int f = 0; f < F; ++f) {
        float xv = xr[f];
        float wa = wr[f];
        float wb = wr[F + f];
        av = fmaf(wa - wb, xv, av);
        cv = fmaf(wb, xv, cv);
    }
    a[i * HDIM + l] = av;
    c[i * HDIM + l] = cv;
}

// ---------- GRU scan: warp-specialized producer/consumer ----------
// CTA = 256 threads = 4 consumer warps (seqs) + 4 producer warps.
// Producer pw: xg_j = Wih @ relu(a_i + c_j) + fused biases, into smem ring.
// Consumer w: hg_j = Whh @ h_{j-1}; gates; recurrence. Reads xg via 3 LDS.
// Ring: chunk k lives in buf k&1; producer runs one chunk ahead.
template <int FUSE_CLF>
__global__ void __launch_bounds__(256, 2)
gru_scan_kernel(const float* __restrict__ a, const float* __restrict__ c,
                const float* __restrict__ wih, const float* __restrict__ whh,
                const float* __restrict__ bih, const float* __restrict__ bhh,
                const float* __restrict__ clf_w, const float* __restrict__ clf_b,
                float* __restrict__ out) {
    __shared__ __align__(16) float s_xg[2][4][3][T_CHUNK][32]; // [buf][seq][gate][t][lane]
    __shared__ __align__(16) float s_h[4][2][32];              // [seq][parity][lane]
    __shared__ __align__(16) float s_u[4][2][32];              // [prod][parity][lane]

    const int wid = threadIdx.x >> 5;
    const int l = threadIdx.x & 31;

    if (wid < 4) {
        // ================= consumer =================
        const int w = wid;
        const int i = blockIdx.x * 4 + w;

        u64 Whr[16], Whz[16], Whn[16];
        {
            const u64* phr = (const u64*)(whh + (0 * HDIM + l) * HDIM);
            const u64* phz = (const u64*)(whh + (1 * HDIM + l) * HDIM);
            const u64* phn = (const u64*)(whh + (2 * HDIM + l) * HDIM);
#pragma unroll
            for (int q = 0; q < 16; ++q) {
                Whr[q] = phr[q];
                Whz[q] = phz[q];
                Whn[q] = phn[q];
            }
        }
        const u64 init_n = pack2(bhh[2 * HDIM + l], 0.0f);   // b_hn

        const u32 hb = smem_u32(&s_h[w][0][0]);
        const u32 xb = smem_u32(&s_xg[0][w][0][0][0]);

        float h = 0.0f;

        for (int k = 0; k <= NCHUNK; ++k) {
            if (k > 0) {
                const u32 xc = xb + (u32)((k - 1) & 1) * 12288u;
#pragma unroll
                for (int t = 0; t < T_CHUNK; ++t) {
                    const u32 hoff = hb + (u32)(t & 1) * 128u;
                    sts32(hoff + l * 4u, h);
                    __syncwarp();
                    const float xr = lds32f(xc + t * 128u + l * 4u);
                    const float xz = lds32f(xc + 1024u + t * 128u + l * 4u);
                    const float xn = lds32f(xc + 2048u + t * 128u + l * 4u);
                    u64 r_ = 0ULL, z_ = 0ULL, n_ = init_n;
#pragma unroll
                    for (int q = 0; q < 8; ++q) {
                        u64 p0, p1;
                        lds_v2(p0, p1, hoff + q * 16u);
                        r_ = f2fma(Whr[2 * q], p0, f2fma(Whr[2 * q + 1], p1, r_));
                        z_ = f2fma(Whz[2 * q], p0, f2fma(Whz[2 * q + 1], p1, z_));
                        n_ = f2fma(Whn[2 * q], p0, f2fma(Whn[2 * q + 1], p1, n_));
                    }
                    const float r = sig_hw(xr + hsum2(r_));
                    const float z = sig_hw(xz + hsum2(z_));
                    const float n = tanh_hw(fmaf(r, hsum2(n_), xn));
                    h = fmaf(z, h - n, n);
                }
            }
            barrier_all();
        }

        if (FUSE_CLF) {
            sts32(hb + l * 4u, h);
            __syncwarp();
            if (l < 3) {
                float acc = clf_b[l];
                const float* cw = clf_w + l * HDIM;
#pragma unroll
                for (int hh = 0; hh < HDIM; ++hh)
                    acc = fmaf(cw[hh], s_h[w][0][hh], acc);
                out[i * 3 + l] = acc;
            }
        } else {
            out[i * HDIM + l] = h;
        }
    } else {
        // ================= producer =================
        const int pw = wid - 4;
        const int i = blockIdx.x * 4 + pw;

        u64 Wxr[16], Wxz[16], Wxn[16];
        {
            const u64* pxr = (const u64*)(wih + (0 * HDIM + l) * HDIM);
            const u64* pxz = (const u64*)(wih + (1 * HDIM + l) * HDIM);
            const u64* pxn = (const u64*)(wih + (2 * HDIM + l) * HDIM);
#pragma unroll
            for (int q = 0; q < 16; ++q) {
                Wxr[q] = pxr[q];
                Wxz[q] = pxz[q];
                Wxn[q] = pxn[q];
            }
        }
        // fused biases: r,z get bih+bhh; n gets bih only (b_hn stays consumer-side)
        const float B_r = bih[l] + bhh[l];
        const float B_z = bih[HDIM + l] + bhh[HDIM + l];
        const float B_n = bih[2 * HDIM + l];
        const float a_l = a[i * HDIM + l];

        const u32 ubuf = smem_u32(&s_u[pw][0][0]);
        const u32 xb = smem_u32(&s_xg[0][pw][0][0][0]);

        float cn = c[l];   // c_0

        for (int k = 0; k <= NCHUNK; ++k) {
            if (k < NCHUNK) {
                const u32 xc = xb + (u32)(k & 1) * 12288u;
                const int j0 = k * T_CHUNK;
#pragma unroll
                for (int t = 0; t < T_CHUNK; ++t) {
                    const float u = fmaxf(a_l + cn, 0.0f);
                    cn = c[(j0 + t + 1) * HDIM + l];   // pad rows are zero
                    const u32 uoff = ubuf + (u32)(t & 1) * 128u;
                    sts32(uoff + l * 4u, u);
                    __syncwarp();
                    u64 r_ = 0ULL, z_ = 0ULL, n_ = 0ULL;
#pragma unroll
                    for (int q = 0; q < 8; ++q) {
                        u64 p0, p1;
                        lds_v2(p0, p1, uoff + q * 16u);
                        r_ = f2fma(Wxr[2 * q], p0, f2fma(Wxr[2 * q + 1], p1, r_));
                        z_ = f2fma(Wxz[2 * q], p0, f2fma(Wxz[2 * q + 1], p1, z_));
                        n_ = f2fma(Wxn[2 * q], p0, f2fma(Wxn[2 * q + 1], p1, n_));
                    }
                    sts32(xc + t * 128u + l * 4u, hsum2(r_) + B_r);
                    sts32(xc + 1024u + t * 128u + l * 4u, hsum2(z_) + B_z);
                    sts32(xc + 2048u + t * 128u + l * 4u, hsum2(n_) + B_n);
                }
            }
            barrier_all();
        }
    }
}

extern "C" void kernel_launch(void* const* d_in, const int* in_sizes, int n_in,
                              void* d_out, int out_size) {
    const float* x        = (const float*)d_in[0];
    const float* proj1_w  = (const float*)d_in[1];
    const float* proj1_b  = (const float*)d_in[2];
    const float* gru1_wih = (const float*)d_in[3];
    const float* gru1_whh = (const float*)d_in[4];
    const float* gru1_bih = (const float*)d_in[5];
    const float* gru1_bhh = (const float*)d_in[6];
    const float* proj2_w  = (const float*)d_in[7];
    const float* proj2_b  = (const float*)d_in[8];
    const float* gru2_wih = (const float*)d_in[9];
    const float* gru2_whh = (const float*)d_in[10];
    const float* gru2_bih = (const float*)d_in[11];
    const float* gru2_bhh = (const float*)d_in[12];
    const float* clf_w    = (const float*)d_in[13];
    const float* clf_b    = (const float*)d_in[14];
    float* out = (float*)d_out;

    float *pa, *pc, *ph1;
    cudaGetSymbolAddress((void**)&pa, g_a);
    cudaGetSymbolAddress((void**)&pc, g_c);
    cudaGetSymbolAddress((void**)&ph1, g_h1);

    pre_kernel<16><<<128, 256>>>(x, proj1_w, proj1_b, pa, pc);
    gru_scan_kernel<0><<<256, 256>>>(pa, pc, gru1_wih, gru1_whh, gru1_bih,
                                     gru1_bhh, nullptr, nullptr, ph1);
    pre_kernel<32><<<128, 256>>>(ph1, proj2_w, proj2_b, pa, pc);
    gru_scan_kernel<1><<<256, 256>>>(pa, pc, gru2_wih, gru2_whh, gru2_bih,
                                     gru2_bhh, clf_w, clf_b, out);
}